// round 2
// baseline (speedup 1.0000x reference)
#include <cuda_runtime.h>
#include <cuda_bf16.h>
#include <cstddef>

// ---------------------------------------------------------------------------
// Shapes (fixed by the problem)
// ---------------------------------------------------------------------------
#define B_      8
#define L_      1024
#define D_      1024
#define H_      16
#define DH_     64
#define DT_     256
#define HID_    4096
#define ROWS_   (B_ * L_)          // 8192
#define BH_     (B_ * H_)          // 128

// ---------------------------------------------------------------------------
// Static device scratch (allocation-free rule: __device__ globals)
// ---------------------------------------------------------------------------
__device__ float d_gb[4][B_ * D_];                         // g1,b1,g2,b2  [B,D]
__device__ float d_xn [ROWS_ * D_];                        // normed x
__device__ float d_q  [ROWS_ * D_];                        // [B,L,D]
__device__ float d_k  [ROWS_ * D_];
__device__ float d_v  [ROWS_ * D_];
__device__ float d_s  [(size_t)BH_ * L_ * L_];             // scores / probs (512MB)
__device__ float d_ao [ROWS_ * D_];                        // attention out [B,L,D]
__device__ float d_x1 [ROWS_ * D_];                        // x + attn
__device__ float d_gate[ROWS_ * HID_];
__device__ float d_hid [ROWS_ * HID_];

// ---------------------------------------------------------------------------
// Reductions
// ---------------------------------------------------------------------------
__device__ __forceinline__ float warpSum(float v) {
    #pragma unroll
    for (int o = 16; o; o >>= 1) v += __shfl_xor_sync(0xffffffffu, v, o);
    return v;
}
__device__ __forceinline__ float warpMax(float v) {
    #pragma unroll
    for (int o = 16; o; o >>= 1) v = fmaxf(v, __shfl_xor_sync(0xffffffffu, v, o));
    return v;
}

// ---------------------------------------------------------------------------
// 1) gamma/beta from t:  out[sel][b][d] = t[b,:] . w[d,:] + bias[d]
// ---------------------------------------------------------------------------
__global__ void k_gamma_beta(const float* __restrict__ t,
                             const float* __restrict__ g1w, const float* __restrict__ g1b,
                             const float* __restrict__ b1w, const float* __restrict__ b1b,
                             const float* __restrict__ g2w, const float* __restrict__ g2b,
                             const float* __restrict__ b2w, const float* __restrict__ b2b) {
    int idx = blockIdx.x * blockDim.x + threadIdx.x;      // 0..32767
    int sel = idx >> 13;
    int b   = (idx >> 10) & 7;
    int d   = idx & (D_ - 1);
    const float* w; const float* bias;
    if      (sel == 0) { w = g1w; bias = g1b; }
    else if (sel == 1) { w = b1w; bias = b1b; }
    else if (sel == 2) { w = g2w; bias = g2b; }
    else               { w = b2w; bias = b2b; }
    const float4* tr = (const float4*)(t + b * DT_);
    const float4* wr = (const float4*)(w + (size_t)d * DT_);
    float acc = 0.f;
    #pragma unroll
    for (int j = 0; j < DT_ / 4; j++) {
        float4 a = tr[j], c = wr[j];
        acc += a.x * c.x + a.y * c.y + a.z * c.z + a.w * c.w;
    }
    d_gb[sel][b * D_ + d] = acc + bias[d];
}

// ---------------------------------------------------------------------------
// 2) time-conditioned RMSNorm:  out = g * x * rsqrt(mean(x^2)+eps) + b
//    one block per row; 256 threads; float4
// ---------------------------------------------------------------------------
__global__ void k_rmsnorm(const float* __restrict__ x, float* __restrict__ out,
                          int selg, int selb) {
    __shared__ float sh[8];
    __shared__ float bcast;
    int row = blockIdx.x;
    int b   = row >> 10;
    int tid = threadIdx.x;
    const float4* xr = (const float4*)x + (size_t)row * (D_ / 4);
    float4 v = xr[tid];
    float ss = v.x * v.x + v.y * v.y + v.z * v.z + v.w * v.w;
    ss = warpSum(ss);
    if ((tid & 31) == 0) sh[tid >> 5] = ss;
    __syncthreads();
    if (tid < 32) {
        float a = (tid < 8) ? sh[tid] : 0.f;
        a = warpSum(a);
        if (tid == 0) bcast = a;
    }
    __syncthreads();
    float inv = rsqrtf(bcast * (1.0f / D_) + 1e-6f);
    const float4* g  = (const float4*)(d_gb[selg] + b * D_);
    const float4* bb = (const float4*)(d_gb[selb] + b * D_);
    float4 gv = g[tid], bv = bb[tid], r;
    r.x = gv.x * v.x * inv + bv.x;
    r.y = gv.y * v.y * inv + bv.y;
    r.z = gv.z * v.z * inv + bv.z;
    r.w = gv.w * v.w * inv + bv.w;
    ((float4*)out + (size_t)row * (D_ / 4))[tid] = r;
}

// ---------------------------------------------------------------------------
// 3) GEMM: C[M,N] = A[M,K] . W[N,K]^T  (+ optional residual)
//    128x128 block tile, BK=8, 256 threads, 8x8 micro-tile
// ---------------------------------------------------------------------------
__global__ __launch_bounds__(256) void k_gemm_nt(
        const float* __restrict__ A, const float* __restrict__ W,
        const float* __restrict__ res, float* __restrict__ C,
        int M, int N, int K) {
    __shared__ float As[8][128];
    __shared__ float Bs[8][128];
    int tid = threadIdx.x;
    int bm = blockIdx.y * 128, bn = blockIdx.x * 128;
    int lr = tid >> 1;            // 0..127
    int lk = (tid & 1) * 4;       // 0 / 4
    const float* Ag = A + (size_t)(bm + lr) * K + lk;
    const float* Wg = W + (size_t)(bn + lr) * K + lk;
    int tm = (tid >> 4) * 8;
    int tn = (tid & 15) * 8;
    float acc[8][8] = {};
    for (int k0 = 0; k0 < K; k0 += 8) {
        float4 av = *(const float4*)(Ag + k0);
        float4 wv = *(const float4*)(Wg + k0);
        As[lk + 0][lr] = av.x; As[lk + 1][lr] = av.y;
        As[lk + 2][lr] = av.z; As[lk + 3][lr] = av.w;
        Bs[lk + 0][lr] = wv.x; Bs[lk + 1][lr] = wv.y;
        Bs[lk + 2][lr] = wv.z; Bs[lk + 3][lr] = wv.w;
        __syncthreads();
        #pragma unroll
        for (int kk = 0; kk < 8; kk++) {
            float a[8], b[8];
            *(float4*)(a)     = *(const float4*)&As[kk][tm];
            *(float4*)(a + 4) = *(const float4*)&As[kk][tm + 4];
            *(float4*)(b)     = *(const float4*)&Bs[kk][tn];
            *(float4*)(b + 4) = *(const float4*)&Bs[kk][tn + 4];
            #pragma unroll
            for (int i = 0; i < 8; i++)
                #pragma unroll
                for (int j = 0; j < 8; j++)
                    acc[i][j] += a[i] * b[j];
        }
        __syncthreads();
    }
    #pragma unroll
    for (int i = 0; i < 8; i++) {
        size_t ro = (size_t)(bm + tm + i) * N + bn + tn;
        float4 r0 = make_float4(acc[i][0], acc[i][1], acc[i][2], acc[i][3]);
        float4 r1 = make_float4(acc[i][4], acc[i][5], acc[i][6], acc[i][7]);
        if (res) {
            float4 q0 = *(const float4*)(res + ro);
            float4 q1 = *(const float4*)(res + ro + 4);
            r0.x += q0.x; r0.y += q0.y; r0.z += q0.z; r0.w += q0.w;
            r1.x += q1.x; r1.y += q1.y; r1.z += q1.z; r1.w += q1.w;
        }
        *(float4*)(C + ro)     = r0;
        *(float4*)(C + ro + 4) = r1;
    }
}

// ---------------------------------------------------------------------------
// 4) scores: S[bh][i][j] = (1/8) * q[b,i,h,:] . k[b,j,h,:]
//    grid (jt=16, it=16, bh=128); 64x64 tile, K=64 in one shot
// ---------------------------------------------------------------------------
__global__ __launch_bounds__(256) void k_scores(const float* __restrict__ q,
                                                const float* __restrict__ kmat,
                                                float* __restrict__ s) {
    __shared__ float Qs[64][64];   // [d][i]
    __shared__ float Ks[64][64];   // [d][j]
    int tid = threadIdx.x;
    int jt = blockIdx.x, it = blockIdx.y, bh = blockIdx.z;
    int b = bh >> 4, h = bh & 15;
    int row = tid >> 2;
    int seg = (tid & 3) * 16;
    const float* qg = q    + ((size_t)(b * L_ + it * 64 + row)) * D_ + h * DH_ + seg;
    const float* kg = kmat + ((size_t)(b * L_ + jt * 64 + row)) * D_ + h * DH_ + seg;
    #pragma unroll
    for (int i = 0; i < 4; i++) {
        float4 a = *(const float4*)(qg + i * 4);
        float4 c = *(const float4*)(kg + i * 4);
        int d = seg + i * 4;
        Qs[d][row] = a.x; Qs[d + 1][row] = a.y; Qs[d + 2][row] = a.z; Qs[d + 3][row] = a.w;
        Ks[d][row] = c.x; Ks[d + 1][row] = c.y; Ks[d + 2][row] = c.z; Ks[d + 3][row] = c.w;
    }
    __syncthreads();
    int i0 = (tid >> 4) * 4, j0 = (tid & 15) * 4;
    float acc[4][4] = {};
    #pragma unroll
    for (int d = 0; d < 64; d++) {
        float4 av = *(const float4*)&Qs[d][i0];
        float4 bv = *(const float4*)&Ks[d][j0];
        float a[4] = {av.x, av.y, av.z, av.w};
        float c[4] = {bv.x, bv.y, bv.z, bv.w};
        #pragma unroll
        for (int ii = 0; ii < 4; ii++)
            #pragma unroll
            for (int jj = 0; jj < 4; jj++)
                acc[ii][jj] += a[ii] * c[jj];
    }
    #pragma unroll
    for (int ii = 0; ii < 4; ii++) {
        size_t off = ((size_t)bh * L_ + it * 64 + i0 + ii) * L_ + jt * 64 + j0;
        float4 r = make_float4(acc[ii][0] * 0.125f, acc[ii][1] * 0.125f,
                               acc[ii][2] * 0.125f, acc[ii][3] * 0.125f);
        *(float4*)(s + off) = r;
    }
}

// ---------------------------------------------------------------------------
// 5) softmax over last axis, in place; one block per row (131072 rows)
// ---------------------------------------------------------------------------
__global__ void k_softmax(float* __restrict__ s) {
    __shared__ float sh1[8], sh2[8];
    __shared__ float bmax, bsum;
    int tid = threadIdx.x;
    float4* p = (float4*)(s + (size_t)blockIdx.x * L_);
    float4 v = p[tid];
    float m = fmaxf(fmaxf(v.x, v.y), fmaxf(v.z, v.w));
    m = warpMax(m);
    if ((tid & 31) == 0) sh1[tid >> 5] = m;
    __syncthreads();
    if (tid < 32) {
        float a = (tid < 8) ? sh1[tid] : -3.4e38f;
        a = warpMax(a);
        if (tid == 0) bmax = a;
    }
    __syncthreads();
    m = bmax;
    v.x = __expf(v.x - m); v.y = __expf(v.y - m);
    v.z = __expf(v.z - m); v.w = __expf(v.w - m);
    float sum = v.x + v.y + v.z + v.w;
    sum = warpSum(sum);
    if ((tid & 31) == 0) sh2[tid >> 5] = sum;
    __syncthreads();
    if (tid < 32) {
        float a = (tid < 8) ? sh2[tid] : 0.f;
        a = warpSum(a);
        if (tid == 0) bsum = a;
    }
    __syncthreads();
    float r = 1.0f / bsum;
    v.x *= r; v.y *= r; v.z *= r; v.w *= r;
    p[tid] = v;
}

// ---------------------------------------------------------------------------
// 6) PV: O[b,l,h,d] = sum_j P[bh][l][j] * v[b,j,h,d]  -> written to [B,L,D]
//    grid (lt=16, bh=128); 64(l) x 64(d), K=1024 in 64-chunks
// ---------------------------------------------------------------------------
__global__ __launch_bounds__(256) void k_pv(const float* __restrict__ p,
                                            const float* __restrict__ vmat,
                                            float* __restrict__ o) {
    __shared__ float Ps[64][64];   // [j][l]
    __shared__ float Vs[64][64];   // [j][d]
    int tid = threadIdx.x;
    int lt = blockIdx.x, bh = blockIdx.y;
    int b = bh >> 4, h = bh & 15;
    int row = tid >> 2;
    int seg = (tid & 3) * 16;
    int l0 = (tid >> 4) * 4, d0 = (tid & 15) * 4;
    float acc[4][4] = {};
    for (int jc = 0; jc < L_; jc += 64) {
        const float* pg = p    + ((size_t)bh * L_ + lt * 64 + row) * L_ + jc + seg;
        const float* vg = vmat + ((size_t)(b * L_ + jc + row)) * D_ + h * DH_ + seg;
        #pragma unroll
        for (int i = 0; i < 4; i++) {
            float4 a = *(const float4*)(pg + i * 4);
            int j = seg + i * 4;
            Ps[j][row] = a.x; Ps[j + 1][row] = a.y; Ps[j + 2][row] = a.z; Ps[j + 3][row] = a.w;
            *(float4*)&Vs[row][seg + i * 4] = *(const float4*)(vg + i * 4);
        }
        __syncthreads();
        #pragma unroll
        for (int j = 0; j < 64; j++) {
            float4 av = *(const float4*)&Ps[j][l0];
            float4 bv = *(const float4*)&Vs[j][d0];
            float a[4] = {av.x, av.y, av.z, av.w};
            float c[4] = {bv.x, bv.y, bv.z, bv.w};
            #pragma unroll
            for (int ii = 0; ii < 4; ii++)
                #pragma unroll
                for (int jj = 0; jj < 4; jj++)
                    acc[ii][jj] += a[ii] * c[jj];
        }
        __syncthreads();
    }
    #pragma unroll
    for (int ii = 0; ii < 4; ii++) {
        size_t off = ((size_t)(b * L_ + lt * 64 + l0 + ii)) * D_ + h * DH_ + d0;
        *(float4*)(o + off) = make_float4(acc[ii][0], acc[ii][1], acc[ii][2], acc[ii][3]);
    }
}

// ---------------------------------------------------------------------------
// 7) swiglu elementwise:  g <- silu(g) * h
// ---------------------------------------------------------------------------
__global__ void k_swiglu(float* __restrict__ g, const float* __restrict__ h) {
    size_t i = (size_t)blockIdx.x * blockDim.x + threadIdx.x;
    float4 gv = ((float4*)g)[i];
    float4 hv = ((const float4*)h)[i];
    gv.x = gv.x / (1.f + __expf(-gv.x)) * hv.x;
    gv.y = gv.y / (1.f + __expf(-gv.y)) * hv.y;
    gv.z = gv.z / (1.f + __expf(-gv.z)) * hv.z;
    gv.w = gv.w / (1.f + __expf(-gv.w)) * hv.w;
    ((float4*)g)[i] = gv;
}

// ---------------------------------------------------------------------------
// Host launcher
// ---------------------------------------------------------------------------
extern "C" void kernel_launch(void* const* d_in, const int* in_sizes, int n_in,
                              void* d_out, int out_size) {
    const float* x     = (const float*)d_in[0];
    const float* t     = (const float*)d_in[1];
    const float* Wq    = (const float*)d_in[2];
    const float* Wk    = (const float*)d_in[3];
    const float* Wv    = (const float*)d_in[4];
    const float* Wo    = (const float*)d_in[5];
    const float* g1w   = (const float*)d_in[6];
    const float* g1b   = (const float*)d_in[7];
    const float* b1w   = (const float*)d_in[8];
    const float* b1b   = (const float*)d_in[9];
    const float* g2w   = (const float*)d_in[10];
    const float* g2b   = (const float*)d_in[11];
    const float* b2w   = (const float*)d_in[12];
    const float* b2b   = (const float*)d_in[13];
    const float* gatew = (const float*)d_in[14];
    const float* hidw  = (const float*)d_in[15];
    const float* outw  = (const float*)d_in[16];
    float* out = (float*)d_out;

    float *xn, *q, *k, *v, *s, *ao, *x1, *gate, *hid;
    cudaGetSymbolAddress((void**)&xn,   d_xn);
    cudaGetSymbolAddress((void**)&q,    d_q);
    cudaGetSymbolAddress((void**)&k,    d_k);
    cudaGetSymbolAddress((void**)&v,    d_v);
    cudaGetSymbolAddress((void**)&s,    d_s);
    cudaGetSymbolAddress((void**)&ao,   d_ao);
    cudaGetSymbolAddress((void**)&x1,   d_x1);
    cudaGetSymbolAddress((void**)&gate, d_gate);
    cudaGetSymbolAddress((void**)&hid,  d_hid);

    // gamma/beta for both norms
    k_gamma_beta<<<128, 256>>>(t, g1w, g1b, b1w, b1b, g2w, g2b, b2w, b2b);

    // norm1
    k_rmsnorm<<<ROWS_, 256>>>(x, xn, 0, 1);

    // QKV projections
    dim3 g1024(D_ / 128, ROWS_ / 128);     // (8, 64)
    dim3 g4096(HID_ / 128, ROWS_ / 128);   // (32, 64)
    k_gemm_nt<<<g1024, 256>>>(xn, Wq, nullptr, q, ROWS_, D_, D_);
    k_gemm_nt<<<g1024, 256>>>(xn, Wk, nullptr, k, ROWS_, D_, D_);
    k_gemm_nt<<<g1024, 256>>>(xn, Wv, nullptr, v, ROWS_, D_, D_);

    // attention
    k_scores<<<dim3(L_ / 64, L_ / 64, BH_), 256>>>(q, k, s);
    k_softmax<<<BH_ * L_, 256>>>(s);
    k_pv<<<dim3(L_ / 64, BH_), 256>>>(s, v, ao);

    // output projection + residual
    k_gemm_nt<<<g1024, 256>>>(ao, Wo, x, x1, ROWS_, D_, D_);

    // norm2
    k_rmsnorm<<<ROWS_, 256>>>(x1, xn, 2, 3);

    // MLP
    k_gemm_nt<<<g4096, 256>>>(xn, gatew, nullptr, gate, ROWS_, HID_, D_);
    k_gemm_nt<<<g4096, 256>>>(xn, hidw,  nullptr, hid,  ROWS_, HID_, D_);
    k_swiglu<<<(ROWS_ * HID_ / 4) / 256, 256>>>(gate, hid);
    k_gemm_nt<<<g1024, 256>>>(gate, outw, x1, out, ROWS_, D_, HID_);
}

// round 7
// speedup vs baseline: 2.0778x; 2.0778x over previous
#include <cuda_runtime.h>
#include <cuda_bf16.h>
#include <cstdint>
#include <cstddef>

// ---------------------------------------------------------------------------
// Shapes
// ---------------------------------------------------------------------------
#define B_      8
#define L_      1024
#define D_      1024
#define H_      16
#define DH_     64
#define DT_     256
#define HID_    4096
#define ROWS_   (B_ * L_)          // 8192
#define BH_     (B_ * H_)          // 128
#define K3D_    (3 * D_)           // 3072
#define K3H_    (3 * HID_)         // 12288

// ---------------------------------------------------------------------------
// Static device scratch
// ---------------------------------------------------------------------------
__device__ float d_gb[4][B_ * D_];
__device__ float d_q  [ROWS_ * D_];
__device__ float d_k  [ROWS_ * D_];
__device__ float d_v  [ROWS_ * D_];
__device__ float d_s  [(size_t)BH_ * L_ * L_];
__device__ float d_ao [ROWS_ * D_];
__device__ float d_x1 [ROWS_ * D_];
__device__ float d_gate[ROWS_ * HID_];
__device__ float d_hid [ROWS_ * HID_];

// bf16 split operands (activations hi|hi|lo, weights hi|lo|hi)
__device__ __nv_bfloat16 d_xn3 [(size_t)ROWS_ * K3D_];
__device__ __nv_bfloat16 d_ao3 [(size_t)ROWS_ * K3D_];
__device__ __nv_bfloat16 d_ga3 [(size_t)ROWS_ * K3H_];
__device__ __nv_bfloat16 d_wq3 [(size_t)D_ * K3D_];
__device__ __nv_bfloat16 d_wk3 [(size_t)D_ * K3D_];
__device__ __nv_bfloat16 d_wv3 [(size_t)D_ * K3D_];
__device__ __nv_bfloat16 d_wo3 [(size_t)D_ * K3D_];
__device__ __nv_bfloat16 d_wg3 [(size_t)HID_ * K3D_];
__device__ __nv_bfloat16 d_wh3 [(size_t)HID_ * K3D_];
__device__ __nv_bfloat16 d_wu3 [(size_t)D_ * K3H_];

// ---------------------------------------------------------------------------
// Helpers
// ---------------------------------------------------------------------------
__device__ __forceinline__ uint32_t smem_u32(const void* p) {
    uint32_t a;
    asm("{ .reg .u64 t; cvta.to.shared.u64 t, %1; cvt.u32.u64 %0, t; }" : "=r"(a) : "l"(p));
    return a;
}
__device__ __forceinline__ void cp16(uint32_t s, const void* g) {
    asm volatile("cp.async.cg.shared.global [%0], [%1], 16;" :: "r"(s), "l"(g));
}
__device__ __forceinline__ void cp_commit() {
    asm volatile("cp.async.commit_group;" ::: "memory");
}
__device__ __forceinline__ void cp_wait1() {
    asm volatile("cp.async.wait_group 1;" ::: "memory");
}
__device__ __forceinline__ void ldsm4(uint32_t* r, uint32_t a) {
    asm volatile("ldmatrix.sync.aligned.m8n8.x4.shared.b16 {%0,%1,%2,%3}, [%4];"
                 : "=r"(r[0]), "=r"(r[1]), "=r"(r[2]), "=r"(r[3]) : "r"(a));
}
__device__ __forceinline__ void mma16816(float* c, const uint32_t* a, uint32_t b0, uint32_t b1) {
    asm volatile("mma.sync.aligned.m16n8k16.row.col.f32.bf16.bf16.f32 "
                 "{%0,%1,%2,%3}, {%4,%5,%6,%7}, {%8,%9}, {%0,%1,%2,%3};"
                 : "+f"(c[0]), "+f"(c[1]), "+f"(c[2]), "+f"(c[3])
                 : "r"(a[0]), "r"(a[1]), "r"(a[2]), "r"(a[3]), "r"(b0), "r"(b1));
}
__device__ __forceinline__ float warpSum(float v) {
    #pragma unroll
    for (int o = 16; o; o >>= 1) v += __shfl_xor_sync(0xffffffffu, v, o);
    return v;
}
__device__ __forceinline__ float warpMax(float v) {
    #pragma unroll
    for (int o = 16; o; o >>= 1) v = fmaxf(v, __shfl_xor_sync(0xffffffffu, v, o));
    return v;
}
__device__ __forceinline__ void split2(float x, __nv_bfloat16& hi, __nv_bfloat16& lo) {
    hi = __float2bfloat16(x);
    lo = __float2bfloat16(x - __bfloat162float(hi));
}

// ---------------------------------------------------------------------------
// 1) gamma/beta from t
// ---------------------------------------------------------------------------
__global__ void k_gamma_beta(const float* __restrict__ t,
                             const float* __restrict__ g1w, const float* __restrict__ g1b,
                             const float* __restrict__ b1w, const float* __restrict__ b1b,
                             const float* __restrict__ g2w, const float* __restrict__ g2b,
                             const float* __restrict__ b2w, const float* __restrict__ b2b) {
    int idx = blockIdx.x * blockDim.x + threadIdx.x;
    int sel = idx >> 13;
    int b   = (idx >> 10) & 7;
    int d   = idx & (D_ - 1);
    const float* w; const float* bias;
    if      (sel == 0) { w = g1w; bias = g1b; }
    else if (sel == 1) { w = b1w; bias = b1b; }
    else if (sel == 2) { w = g2w; bias = g2b; }
    else               { w = b2w; bias = b2b; }
    const float4* tr = (const float4*)(t + b * DT_);
    const float4* wr = (const float4*)(w + (size_t)d * DT_);
    float acc = 0.f;
    #pragma unroll
    for (int j = 0; j < DT_ / 4; j++) {
        float4 a = tr[j], c = wr[j];
        acc += a.x * c.x + a.y * c.y + a.z * c.z + a.w * c.w;
    }
    d_gb[sel][b * D_ + d] = acc + bias[d];
}

// ---------------------------------------------------------------------------
// 2) RMSNorm fused with bf16 triple conversion (hi|hi|lo)
// ---------------------------------------------------------------------------
__global__ void k_rmsnorm_cvt(const float* __restrict__ x, __nv_bfloat16* __restrict__ out3,
                              int selg, int selb) {
    __shared__ float sh[8];
    __shared__ float bcast;
    int row = blockIdx.x;
    int b   = row >> 10;
    int tid = threadIdx.x;
    const float4* xr = (const float4*)x + (size_t)row * (D_ / 4);
    float4 v = xr[tid];
    float ss = v.x * v.x + v.y * v.y + v.z * v.z + v.w * v.w;
    ss = warpSum(ss);
    if ((tid & 31) == 0) sh[tid >> 5] = ss;
    __syncthreads();
    if (tid < 32) {
        float a = (tid < 8) ? sh[tid] : 0.f;
        a = warpSum(a);
        if (tid == 0) bcast = a;
    }
    __syncthreads();
    float inv = rsqrtf(bcast * (1.0f / D_) + 1e-6f);
    const float4* g  = (const float4*)(d_gb[selg] + b * D_);
    const float4* bb = (const float4*)(d_gb[selb] + b * D_);
    float4 gv = g[tid], bv = bb[tid], r;
    r.x = gv.x * v.x * inv + bv.x;
    r.y = gv.y * v.y * inv + bv.y;
    r.z = gv.z * v.z * inv + bv.z;
    r.w = gv.w * v.w * inv + bv.w;
    __nv_bfloat16 hx, lx, hy, ly, hz, lz, hw, lw;
    split2(r.x, hx, lx); split2(r.y, hy, ly); split2(r.z, hz, lz); split2(r.w, hw, lw);
    __nv_bfloat16* o = out3 + (size_t)row * K3D_ + tid * 4;
    __nv_bfloat162 hi0 = {hx, hy}, hi1 = {hz, hw};
    __nv_bfloat162 lo0 = {lx, ly}, lo1 = {lz, lw};
    *(uint2*)(o)          = make_uint2(*(uint32_t*)&hi0, *(uint32_t*)&hi1);
    *(uint2*)(o + D_)     = make_uint2(*(uint32_t*)&hi0, *(uint32_t*)&hi1);
    *(uint2*)(o + 2 * D_) = make_uint2(*(uint32_t*)&lo0, *(uint32_t*)&lo1);
}

// ---------------------------------------------------------------------------
// 3) fp32 -> bf16 triple conversion; mode 0: hi|hi|lo, mode 1: hi|lo|hi
// ---------------------------------------------------------------------------
__global__ void k_cvt3(const float* __restrict__ in, __nv_bfloat16* __restrict__ out,
                       int K, int mode) {
    size_t idx4 = (size_t)blockIdx.x * blockDim.x + threadIdx.x;
    int k4 = K >> 2;
    size_t r  = idx4 / k4;
    int    c4 = (int)(idx4 - r * k4);
    float4 v = ((const float4*)in)[idx4];
    __nv_bfloat16 hx, lx, hy, ly, hz, lz, hw, lw;
    split2(v.x, hx, lx); split2(v.y, hy, ly); split2(v.z, hz, lz); split2(v.w, hw, lw);
    __nv_bfloat162 hi0 = {hx, hy}, hi1 = {hz, hw};
    __nv_bfloat162 lo0 = {lx, ly}, lo1 = {lz, lw};
    uint2 HI = make_uint2(*(uint32_t*)&hi0, *(uint32_t*)&hi1);
    uint2 LO = make_uint2(*(uint32_t*)&lo0, *(uint32_t*)&lo1);
    __nv_bfloat16* o = out + r * (size_t)(3 * K) + c4 * 4;
    *(uint2*)(o)         = HI;
    *(uint2*)(o + K)     = mode ? LO : HI;
    *(uint2*)(o + 2 * K) = mode ? HI : LO;
}

// ---------------------------------------------------------------------------
// 4) swiglu fused with triple conversion (hi|hi|lo)
// ---------------------------------------------------------------------------
__global__ void k_swiglu_cvt(const float* __restrict__ g, const float* __restrict__ h,
                             __nv_bfloat16* __restrict__ out) {
    size_t idx4 = (size_t)blockIdx.x * blockDim.x + threadIdx.x;
    size_t r  = idx4 >> 10;
    int    c4 = (int)(idx4 & 1023);
    float4 gv = ((const float4*)g)[idx4];
    float4 hv = ((const float4*)h)[idx4];
    float4 a;
    a.x = gv.x / (1.f + __expf(-gv.x)) * hv.x;
    a.y = gv.y / (1.f + __expf(-gv.y)) * hv.y;
    a.z = gv.z / (1.f + __expf(-gv.z)) * hv.z;
    a.w = gv.w / (1.f + __expf(-gv.w)) * hv.w;
    __nv_bfloat16 hx, lx, hy, ly, hz, lz, hw, lw;
    split2(a.x, hx, lx); split2(a.y, hy, ly); split2(a.z, hz, lz); split2(a.w, hw, lw);
    __nv_bfloat162 hi0 = {hx, hy}, hi1 = {hz, hw};
    __nv_bfloat162 lo0 = {lx, ly}, lo1 = {lz, lw};
    __nv_bfloat16* o = out + r * (size_t)K3H_ + c4 * 4;
    *(uint2*)(o)            = make_uint2(*(uint32_t*)&hi0, *(uint32_t*)&hi1);
    *(uint2*)(o + HID_)     = make_uint2(*(uint32_t*)&hi0, *(uint32_t*)&hi1);
    *(uint2*)(o + 2 * HID_) = make_uint2(*(uint32_t*)&lo0, *(uint32_t*)&lo1);
}

// ---------------------------------------------------------------------------
// 5) mma.sync bf16 GEMM: C[M,N] = A3[M,K3] . W3[N,K3]^T (+res)
//    128x128 tile, BK=32, 8 warps (2x4), warp tile 64x32, 3-stage cp.async
// ---------------------------------------------------------------------------
#define ASTRIDE   80                      // smem bytes per 32-bf16 row (padded)
#define TILEB     (128 * ASTRIDE)         // 10240
#define GEMM_SMEM (3 * 2 * TILEB)         // 61440

__global__ __launch_bounds__(256, 2) void k_gemm_mma(
        const __nv_bfloat16* __restrict__ A,
        const __nv_bfloat16* __restrict__ Bw,
        const float* __restrict__ res, float* __restrict__ C,
        int N, int K3) {
    extern __shared__ char smem[];
    uint32_t sb = smem_u32(smem);
    int tid = threadIdx.x, lane = tid & 31, wid = tid >> 5;
    int wm = wid >> 2, wn = wid & 3;
    int bm = blockIdx.y * 128, bn = blockIdx.x * 128;

    // cp.async mapping: thread -> (row, 2 chunks of 16B)
    int crow  = tid >> 1;
    int ccol2 = (tid & 1) * 2;
    const __nv_bfloat16* gA = A  + (size_t)(bm + crow) * K3 + ccol2 * 8;
    const __nv_bfloat16* gB = Bw + (size_t)(bn + crow) * K3 + ccol2 * 8;
    uint32_t sOff = crow * ASTRIDE + ccol2 * 16;

    // ldmatrix per-lane offsets
    uint32_t aOff = (uint32_t)((lane & 15) * ASTRIDE + ((lane & 16) ? 16 : 0));
    uint32_t bOff = (uint32_t)(((lane & 7) + ((lane >> 4) & 1) * 8) * ASTRIDE
                               + ((lane >> 3) & 1) * 16);

    float acc[4][4][4] = {};
    int niter = K3 >> 5;

    // prologue: stages 0 and 1
    #pragma unroll
    for (int p = 0; p < 2; p++) {
        uint32_t as = sb + p * 2 * TILEB + sOff;
        const __nv_bfloat16* ag = gA + p * 32;
        const __nv_bfloat16* bg = gB + p * 32;
        cp16(as,      ag);
        cp16(as + 16, ag + 8);
        cp16(as + TILEB,      bg);
        cp16(as + TILEB + 16, bg + 8);
        cp_commit();
    }

    for (int it = 0; it < niter; it++) {
        cp_wait1();
        __syncthreads();
        // issue next stage (into the buffer consumed at it-1)
        int nx = it + 2;
        if (nx < niter) {
            uint32_t as = sb + (nx % 3) * 2 * TILEB + sOff;
            const __nv_bfloat16* ag = gA + nx * 32;
            const __nv_bfloat16* bg = gB + nx * 32;
            cp16(as,      ag);
            cp16(as + 16, ag + 8);
            cp16(as + TILEB,      bg);
            cp16(as + TILEB + 16, bg + 8);
        }
        cp_commit();

        uint32_t Ab = sb + (it % 3) * 2 * TILEB;
        uint32_t Bb = Ab + TILEB;
        #pragma unroll
        for (int ks = 0; ks < 2; ks++) {
            uint32_t a[4][4];
            #pragma unroll
            for (int am = 0; am < 4; am++)
                ldsm4(a[am], Ab + (wm * 64 + am * 16) * ASTRIDE + ks * 32 + aOff);
            uint32_t b[2][4];
            #pragma unroll
            for (int bg2 = 0; bg2 < 2; bg2++)
                ldsm4(b[bg2], Bb + (wn * 32 + bg2 * 16) * ASTRIDE + ks * 32 + bOff);
            #pragma unroll
            for (int am = 0; am < 4; am++)
                #pragma unroll
                for (int bnn = 0; bnn < 4; bnn++)
                    mma16816(acc[am][bnn], a[am],
                             b[bnn >> 1][(bnn & 1) * 2], b[bnn >> 1][(bnn & 1) * 2 + 1]);
        }
    }

    // epilogue
    int g = lane >> 2;
    int mbase = bm + wm * 64;
    int nbase = bn + wn * 32 + (lane & 3) * 2;
    #pragma unroll
    for (int am = 0; am < 4; am++) {
        #pragma unroll
        for (int bnn = 0; bnn < 4; bnn++) {
            int row0 = mbase + am * 16 + g;
            int col  = nbase + bnn * 8;
            float2 v0 = {acc[am][bnn][0], acc[am][bnn][1]};
            float2 v1 = {acc[am][bnn][2], acc[am][bnn][3]};
            size_t o0 = (size_t)row0 * N + col;
            size_t o1 = (size_t)(row0 + 8) * N + col;
            if (res) {
                float2 r0 = *(const float2*)(res + o0);
                float2 r1 = *(const float2*)(res + o1);
                v0.x += r0.x; v0.y += r0.y;
                v1.x += r1.x; v1.y += r1.y;
            }
            *(float2*)(C + o0) = v0;
            *(float2*)(C + o1) = v1;
        }
    }
}

// ---------------------------------------------------------------------------
// 6) attention (fp32 SIMT, unchanged)
// ---------------------------------------------------------------------------
__global__ __launch_bounds__(256) void k_scores(const float* __restrict__ q,
                                                const float* __restrict__ kmat,
                                                float* __restrict__ s) {
    __shared__ float Qs[64][64];
    __shared__ float Ks[64][64];
    int tid = threadIdx.x;
    int jt = blockIdx.x, it = blockIdx.y, bh = blockIdx.z;
    int b = bh >> 4, h = bh & 15;
    int row = tid >> 2;
    int seg = (tid & 3) * 16;
    const float* qg = q    + ((size_t)(b * L_ + it * 64 + row)) * D_ + h * DH_ + seg;
    const float* kg = kmat + ((size_t)(b * L_ + jt * 64 + row)) * D_ + h * DH_ + seg;
    #pragma unroll
    for (int i = 0; i < 4; i++) {
        float4 a = *(const float4*)(qg + i * 4);
        float4 c = *(const float4*)(kg + i * 4);
        int d = seg + i * 4;
        Qs[d][row] = a.x; Qs[d + 1][row] = a.y; Qs[d + 2][row] = a.z; Qs[d + 3][row] = a.w;
        Ks[d][row] = c.x; Ks[d + 1][row] = c.y; Ks[d + 2][row] = c.z; Ks[d + 3][row] = c.w;
    }
    __syncthreads();
    int i0 = (tid >> 4) * 4, j0 = (tid & 15) * 4;
    float acc[4][4] = {};
    #pragma unroll
    for (int d = 0; d < 64; d++) {
        float4 av = *(const float4*)&Qs[d][i0];
        float4 bv = *(const float4*)&Ks[d][j0];
        float a[4] = {av.x, av.y, av.z, av.w};
        float c[4] = {bv.x, bv.y, bv.z, bv.w};
        #pragma unroll
        for (int ii = 0; ii < 4; ii++)
            #pragma unroll
            for (int jj = 0; jj < 4; jj++)
                acc[ii][jj] += a[ii] * c[jj];
    }
    #pragma unroll
    for (int ii = 0; ii < 4; ii++) {
        size_t off = ((size_t)bh * L_ + it * 64 + i0 + ii) * L_ + jt * 64 + j0;
        *(float4*)(s + off) = make_float4(acc[ii][0] * 0.125f, acc[ii][1] * 0.125f,
                                          acc[ii][2] * 0.125f, acc[ii][3] * 0.125f);
    }
}

__global__ void k_softmax(float* __restrict__ s) {
    __shared__ float sh1[8], sh2[8];
    __shared__ float bmax, bsum;
    int tid = threadIdx.x;
    float4* p = (float4*)(s + (size_t)blockIdx.x * L_);
    float4 v = p[tid];
    float m = fmaxf(fmaxf(v.x, v.y), fmaxf(v.z, v.w));
    m = warpMax(m);
    if ((tid & 31) == 0) sh1[tid >> 5] = m;
    __syncthreads();
    if (tid < 32) {
        float a = (tid < 8) ? sh1[tid] : -3.4e38f;
        a = warpMax(a);
        if (tid == 0) bmax = a;
    }
    __syncthreads();
    m = bmax;
    v.x = __expf(v.x - m); v.y = __expf(v.y - m);
    v.z = __expf(v.z - m); v.w = __expf(v.w - m);
    float sum = v.x + v.y + v.z + v.w;
    sum = warpSum(sum);
    if ((tid & 31) == 0) sh2[tid >> 5] = sum;
    __syncthreads();
    if (tid < 32) {
        float a = (tid < 8) ? sh2[tid] : 0.f;
        a = warpSum(a);
        if (tid == 0) bsum = a;
    }
    __syncthreads();
    float r = 1.0f / bsum;
    v.x *= r; v.y *= r; v.z *= r; v.w *= r;
    p[tid] = v;
}

__global__ __launch_bounds__(256) void k_pv(const float* __restrict__ p,
                                            const float* __restrict__ vmat,
                                            float* __restrict__ o) {
    __shared__ float Ps[64][64];
    __shared__ float Vs[64][64];
    int tid = threadIdx.x;
    int lt = blockIdx.x, bh = blockIdx.y;
    int b = bh >> 4, h = bh & 15;
    int row = tid >> 2;
    int seg = (tid & 3) * 16;
    int l0 = (tid >> 4) * 4, d0 = (tid & 15) * 4;
    float acc[4][4] = {};
    for (int jc = 0; jc < L_; jc += 64) {
        const float* pg = p    + ((size_t)bh * L_ + lt * 64 + row) * L_ + jc + seg;
        const float* vg = vmat + ((size_t)(b * L_ + jc + row)) * D_ + h * DH_ + seg;
        #pragma unroll
        for (int i = 0; i < 4; i++) {
            float4 a = *(const float4*)(pg + i * 4);
            int j = seg + i * 4;
            Ps[j][row] = a.x; Ps[j + 1][row] = a.y; Ps[j + 2][row] = a.z; Ps[j + 3][row] = a.w;
            *(float4*)&Vs[row][seg + i * 4] = *(const float4*)(vg + i * 4);
        }
        __syncthreads();
        #pragma unroll
        for (int j = 0; j < 64; j++) {
            float4 av = *(const float4*)&Ps[j][l0];
            float4 bv = *(const float4*)&Vs[j][d0];
            float a[4] = {av.x, av.y, av.z, av.w};
            float c[4] = {bv.x, bv.y, bv.z, bv.w};
            #pragma unroll
            for (int ii = 0; ii < 4; ii++)
                #pragma unroll
                for (int jj = 0; jj < 4; jj++)
                    acc[ii][jj] += a[ii] * c[jj];
        }
        __syncthreads();
    }
    #pragma unroll
    for (int ii = 0; ii < 4; ii++) {
        size_t off = ((size_t)(b * L_ + lt * 64 + l0 + ii)) * D_ + h * DH_ + d0;
        *(float4*)(o + off) = make_float4(acc[ii][0], acc[ii][1], acc[ii][2], acc[ii][3]);
    }
}

// ---------------------------------------------------------------------------
// Host launcher
// ---------------------------------------------------------------------------
extern "C" void kernel_launch(void* const* d_in, const int* in_sizes, int n_in,
                              void* d_out, int out_size) {
    const float* x     = (const float*)d_in[0];
    const float* t     = (const float*)d_in[1];
    const float* Wq    = (const float*)d_in[2];
    const float* Wk    = (const float*)d_in[3];
    const float* Wv    = (const float*)d_in[4];
    const float* Wo    = (const float*)d_in[5];
    const float* g1w   = (const float*)d_in[6];
    const float* g1b   = (const float*)d_in[7];
    const float* b1w   = (const float*)d_in[8];
    const float* b1b   = (const float*)d_in[9];
    const float* g2w   = (const float*)d_in[10];
    const float* g2b   = (const float*)d_in[11];
    const float* b2w   = (const float*)d_in[12];
    const float* b2b   = (const float*)d_in[13];
    const float* gatew = (const float*)d_in[14];
    const float* hidw  = (const float*)d_in[15];
    const float* outw  = (const float*)d_in[16];
    float* out = (float*)d_out;

    float *q, *k, *v, *s, *ao, *x1, *gate, *hid;
    __nv_bfloat16 *xn3, *ao3, *ga3, *wq3, *wk3, *wv3, *wo3, *wg3, *wh3, *wu3;
    cudaGetSymbolAddress((void**)&q,    d_q);
    cudaGetSymbolAddress((void**)&k,    d_k);
    cudaGetSymbolAddress((void**)&v,    d_v);
    cudaGetSymbolAddress((void**)&s,    d_s);
    cudaGetSymbolAddress((void**)&ao,   d_ao);
    cudaGetSymbolAddress((void**)&x1,   d_x1);
    cudaGetSymbolAddress((void**)&gate, d_gate);
    cudaGetSymbolAddress((void**)&hid,  d_hid);
    cudaGetSymbolAddress((void**)&xn3,  d_xn3);
    cudaGetSymbolAddress((void**)&ao3,  d_ao3);
    cudaGetSymbolAddress((void**)&ga3,  d_ga3);
    cudaGetSymbolAddress((void**)&wq3,  d_wq3);
    cudaGetSymbolAddress((void**)&wk3,  d_wk3);
    cudaGetSymbolAddress((void**)&wv3,  d_wv3);
    cudaGetSymbolAddress((void**)&wo3,  d_wo3);
    cudaGetSymbolAddress((void**)&wg3,  d_wg3);
    cudaGetSymbolAddress((void**)&wh3,  d_wh3);
    cudaGetSymbolAddress((void**)&wu3,  d_wu3);

    cudaFuncSetAttribute(k_gemm_mma, cudaFuncAttributeMaxDynamicSharedMemorySize, GEMM_SMEM);

    // weight conversions (hi|lo|hi)
    k_cvt3<<<(D_ * D_ / 4) / 256, 256>>>(Wq, wq3, D_, 1);
    k_cvt3<<<(D_ * D_ / 4) / 256, 256>>>(Wk, wk3, D_, 1);
    k_cvt3<<<(D_ * D_ / 4) / 256, 256>>>(Wv, wv3, D_, 1);
    k_cvt3<<<(D_ * D_ / 4) / 256, 256>>>(Wo, wo3, D_, 1);
    k_cvt3<<<(HID_ * D_ / 4) / 256, 256>>>(gatew, wg3, D_, 1);
    k_cvt3<<<(HID_ * D_ / 4) / 256, 256>>>(hidw,  wh3, D_, 1);
    k_cvt3<<<(D_ * HID_ / 4) / 256, 256>>>(outw,  wu3, HID_, 1);

    // gamma/beta + norm1 (fused convert)
    k_gamma_beta<<<128, 256>>>(t, g1w, g1b, b1w, b1b, g2w, g2b, b2w, b2b);
    k_rmsnorm_cvt<<<ROWS_, 256>>>(x, xn3, 0, 1);

    // QKV projections (tensor cores via mma.sync)
    dim3 gn1024(D_ / 128, ROWS_ / 128);     // (8, 64)
    dim3 gn4096(HID_ / 128, ROWS_ / 128);   // (32, 64)
    k_gemm_mma<<<gn1024, 256, GEMM_SMEM>>>(xn3, wq3, nullptr, q, D_, K3D_);
    k_gemm_mma<<<gn1024, 256, GEMM_SMEM>>>(xn3, wk3, nullptr, k, D_, K3D_);
    k_gemm_mma<<<gn1024, 256, GEMM_SMEM>>>(xn3, wv3, nullptr, v, D_, K3D_);

    // attention (fp32 SIMT)
    k_scores<<<dim3(L_ / 64, L_ / 64, BH_), 256>>>(q, k, s);
    k_softmax<<<BH_ * L_, 256>>>(s);
    k_pv<<<dim3(L_ / 64, BH_), 256>>>(s, v, ao);

    // output projection + residual
    k_cvt3<<<(ROWS_ * D_ / 4) / 256, 256>>>(ao, ao3, D_, 0);
    k_gemm_mma<<<gn1024, 256, GEMM_SMEM>>>(ao3, wo3, x, x1, D_, K3D_);

    // norm2 + MLP
    k_rmsnorm_cvt<<<ROWS_, 256>>>(x1, xn3, 2, 3);
    k_gemm_mma<<<gn4096, 256, GEMM_SMEM>>>(xn3, wg3, nullptr, gate, HID_, K3D_);
    k_gemm_mma<<<gn4096, 256, GEMM_SMEM>>>(xn3, wh3, nullptr, hid,  HID_, K3D_);
    k_swiglu_cvt<<<(ROWS_ * HID_ / 4) / 256, 256>>>(gate, hid, ga3);
    k_gemm_mma<<<gn1024, 256, GEMM_SMEM>>>(ga3, wu3, x1, out, D_, K3H_);
}

// round 8
// speedup vs baseline: 2.1886x; 1.0533x over previous
#include <cuda_runtime.h>
#include <cuda_bf16.h>
#include <cstdint>
#include <cstddef>

// ---------------------------------------------------------------------------
// Shapes
// ---------------------------------------------------------------------------
#define B_      8
#define L_      1024
#define D_      1024
#define H_      16
#define DH_     64
#define DT_     256
#define HID_    4096
#define ROWS_   (B_ * L_)          // 8192
#define BH_     (B_ * H_)          // 128
#define K3D_    (3 * D_)           // 3072
#define K3H_    (3 * HID_)         // 12288

// ---------------------------------------------------------------------------
// Static device scratch
// ---------------------------------------------------------------------------
__device__ float d_gb[4][B_ * D_];
__device__ float d_qkv [(size_t)ROWS_ * 3 * D_];           // fused QKV out (fp32)
__device__ float d_x1  [ROWS_ * D_];
__device__ float d_gate[ROWS_ * HID_];

// bf16 operands
__device__ __nv_bfloat16 d_xn3 [(size_t)ROWS_ * K3D_];     // activations hi|hi|lo
__device__ __nv_bfloat16 d_ao3 [(size_t)ROWS_ * K3D_];
__device__ __nv_bfloat16 d_ga3 [(size_t)ROWS_ * K3H_];
__device__ __nv_bfloat16 d_q3  [(size_t)BH_ * L_ * 192];   // per-head hi|hi|lo
__device__ __nv_bfloat16 d_k3  [(size_t)BH_ * L_ * 192];   // per-head hi|lo|hi
__device__ __nv_bfloat16 d_vh  [(size_t)BH_ * L_ * 64];    // per-head bf16
__device__ __nv_bfloat16 d_wqkv3[(size_t)(3 * D_) * K3D_]; // weights hi|lo|hi
__device__ __nv_bfloat16 d_wo3 [(size_t)D_ * K3D_];
__device__ __nv_bfloat16 d_wg3 [(size_t)HID_ * K3D_];
__device__ __nv_bfloat16 d_wh3 [(size_t)HID_ * K3D_];
__device__ __nv_bfloat16 d_wu3 [(size_t)D_ * K3H_];

// ---------------------------------------------------------------------------
// Helpers
// ---------------------------------------------------------------------------
__device__ __forceinline__ uint32_t smem_u32(const void* p) {
    uint32_t a;
    asm("{ .reg .u64 t; cvta.to.shared.u64 t, %1; cvt.u32.u64 %0, t; }" : "=r"(a) : "l"(p));
    return a;
}
__device__ __forceinline__ void cp16(uint32_t s, const void* g) {
    asm volatile("cp.async.cg.shared.global [%0], [%1], 16;" :: "r"(s), "l"(g));
}
__device__ __forceinline__ void cp_commit() {
    asm volatile("cp.async.commit_group;" ::: "memory");
}
__device__ __forceinline__ void cp_wait1() {
    asm volatile("cp.async.wait_group 1;" ::: "memory");
}
__device__ __forceinline__ void cp_wait0() {
    asm volatile("cp.async.wait_group 0;" ::: "memory");
}
__device__ __forceinline__ void ldsm4(uint32_t* r, uint32_t a) {
    asm volatile("ldmatrix.sync.aligned.m8n8.x4.shared.b16 {%0,%1,%2,%3}, [%4];"
                 : "=r"(r[0]), "=r"(r[1]), "=r"(r[2]), "=r"(r[3]) : "r"(a));
}
__device__ __forceinline__ void ldsm4t(uint32_t* r, uint32_t a) {
    asm volatile("ldmatrix.sync.aligned.m8n8.x4.trans.shared.b16 {%0,%1,%2,%3}, [%4];"
                 : "=r"(r[0]), "=r"(r[1]), "=r"(r[2]), "=r"(r[3]) : "r"(a));
}
__device__ __forceinline__ void mma16816(float* c, const uint32_t* a, uint32_t b0, uint32_t b1) {
    asm volatile("mma.sync.aligned.m16n8k16.row.col.f32.bf16.bf16.f32 "
                 "{%0,%1,%2,%3}, {%4,%5,%6,%7}, {%8,%9}, {%0,%1,%2,%3};"
                 : "+f"(c[0]), "+f"(c[1]), "+f"(c[2]), "+f"(c[3])
                 : "r"(a[0]), "r"(a[1]), "r"(a[2]), "r"(a[3]), "r"(b0), "r"(b1));
}
__device__ __forceinline__ float warpSum(float v) {
    #pragma unroll
    for (int o = 16; o; o >>= 1) v += __shfl_xor_sync(0xffffffffu, v, o);
    return v;
}
__device__ __forceinline__ void split2(float x, __nv_bfloat16& hi, __nv_bfloat16& lo) {
    hi = __float2bfloat16(x);
    lo = __float2bfloat16(x - __bfloat162float(hi));
}
__device__ __forceinline__ uint32_t packbf(float a, float b) {
    __nv_bfloat162 t = __floats2bfloat162_rn(a, b);
    return *(uint32_t*)&t;
}

// ---------------------------------------------------------------------------
// 1) gamma/beta from t
// ---------------------------------------------------------------------------
__global__ void k_gamma_beta(const float* __restrict__ t,
                             const float* __restrict__ g1w, const float* __restrict__ g1b,
                             const float* __restrict__ b1w, const float* __restrict__ b1b,
                             const float* __restrict__ g2w, const float* __restrict__ g2b,
                             const float* __restrict__ b2w, const float* __restrict__ b2b) {
    int idx = blockIdx.x * blockDim.x + threadIdx.x;
    int sel = idx >> 13;
    int b   = (idx >> 10) & 7;
    int d   = idx & (D_ - 1);
    const float* w; const float* bias;
    if      (sel == 0) { w = g1w; bias = g1b; }
    else if (sel == 1) { w = b1w; bias = b1b; }
    else if (sel == 2) { w = g2w; bias = g2b; }
    else               { w = b2w; bias = b2b; }
    const float4* tr = (const float4*)(t + b * DT_);
    const float4* wr = (const float4*)(w + (size_t)d * DT_);
    float acc = 0.f;
    #pragma unroll
    for (int j = 0; j < DT_ / 4; j++) {
        float4 a = tr[j], c = wr[j];
        acc += a.x * c.x + a.y * c.y + a.z * c.z + a.w * c.w;
    }
    d_gb[sel][b * D_ + d] = acc + bias[d];
}

// ---------------------------------------------------------------------------
// 2) RMSNorm fused with bf16 triple conversion (hi|hi|lo)
// ---------------------------------------------------------------------------
__global__ void k_rmsnorm_cvt(const float* __restrict__ x, __nv_bfloat16* __restrict__ out3,
                              int selg, int selb) {
    __shared__ float sh[8];
    __shared__ float bcast;
    int row = blockIdx.x;
    int b   = row >> 10;
    int tid = threadIdx.x;
    const float4* xr = (const float4*)x + (size_t)row * (D_ / 4);
    float4 v = xr[tid];
    float ss = v.x * v.x + v.y * v.y + v.z * v.z + v.w * v.w;
    ss = warpSum(ss);
    if ((tid & 31) == 0) sh[tid >> 5] = ss;
    __syncthreads();
    if (tid < 32) {
        float a = (tid < 8) ? sh[tid] : 0.f;
        a = warpSum(a);
        if (tid == 0) bcast = a;
    }
    __syncthreads();
    float inv = rsqrtf(bcast * (1.0f / D_) + 1e-6f);
    const float4* g  = (const float4*)(d_gb[selg] + b * D_);
    const float4* bb = (const float4*)(d_gb[selb] + b * D_);
    float4 gv = g[tid], bv = bb[tid], r;
    r.x = gv.x * v.x * inv + bv.x;
    r.y = gv.y * v.y * inv + bv.y;
    r.z = gv.z * v.z * inv + bv.z;
    r.w = gv.w * v.w * inv + bv.w;
    __nv_bfloat16 hx, lx, hy, ly, hz, lz, hw, lw;
    split2(r.x, hx, lx); split2(r.y, hy, ly); split2(r.z, hz, lz); split2(r.w, hw, lw);
    __nv_bfloat16* o = out3 + (size_t)row * K3D_ + tid * 4;
    uint2 HI = make_uint2(packbf(__bfloat162float(hx), __bfloat162float(hy)),
                          packbf(__bfloat162float(hz), __bfloat162float(hw)));
    __nv_bfloat162 lo0 = {lx, ly}, lo1 = {lz, lw};
    uint2 LO = make_uint2(*(uint32_t*)&lo0, *(uint32_t*)&lo1);
    *(uint2*)(o)          = HI;
    *(uint2*)(o + D_)     = HI;
    *(uint2*)(o + 2 * D_) = LO;
}

// ---------------------------------------------------------------------------
// 3) fp32 -> bf16 triple conversion (weights, hi|lo|hi)
// ---------------------------------------------------------------------------
__global__ void k_cvt3(const float* __restrict__ in, __nv_bfloat16* __restrict__ out, int K) {
    size_t idx4 = (size_t)blockIdx.x * blockDim.x + threadIdx.x;
    int k4 = K >> 2;
    size_t r  = idx4 / k4;
    int    c4 = (int)(idx4 - r * k4);
    float4 v = ((const float4*)in)[idx4];
    __nv_bfloat16 hx, lx, hy, ly, hz, lz, hw, lw;
    split2(v.x, hx, lx); split2(v.y, hy, ly); split2(v.z, hz, lz); split2(v.w, hw, lw);
    __nv_bfloat162 hi0 = {hx, hy}, hi1 = {hz, hw};
    __nv_bfloat162 lo0 = {lx, ly}, lo1 = {lz, lw};
    uint2 HI = make_uint2(*(uint32_t*)&hi0, *(uint32_t*)&hi1);
    uint2 LO = make_uint2(*(uint32_t*)&lo0, *(uint32_t*)&lo1);
    __nv_bfloat16* o = out + r * (size_t)(3 * K) + c4 * 4;
    *(uint2*)(o)         = HI;
    *(uint2*)(o + K)     = LO;
    *(uint2*)(o + 2 * K) = HI;
}

// ---------------------------------------------------------------------------
// 4) QKV fp32 -> per-head bf16 operands for flash attention
//    q3: hi|hi|lo   k3: hi|lo|hi   vh: bf16
// ---------------------------------------------------------------------------
__global__ void k_qkv3_cvt(const float* __restrict__ qkv,
                           __nv_bfloat16* __restrict__ q3,
                           __nv_bfloat16* __restrict__ k3,
                           __nv_bfloat16* __restrict__ vh) {
    int row = blockIdx.x;           // b*1024 + l
    int b = row >> 10, l = row & 1023;
    int tid = threadIdx.x;
    #pragma unroll
    for (int s3 = 0; s3 < 3; s3++) {
        int idx = s3 * 256 + tid;   // float4 idx 0..767
        int col = idx * 4;
        int sec = col >> 10;
        int h   = (col >> 6) & 15;
        int d   = col & 63;
        float4 v = ((const float4*)(qkv + (size_t)row * 3072))[idx];
        __nv_bfloat16 hx, lx, hy, ly, hz, lz, hw, lw;
        split2(v.x, hx, lx); split2(v.y, hy, ly); split2(v.z, hz, lz); split2(v.w, hw, lw);
        __nv_bfloat162 hi0 = {hx, hy}, hi1 = {hz, hw};
        __nv_bfloat162 lo0 = {lx, ly}, lo1 = {lz, lw};
        uint2 HI = make_uint2(*(uint32_t*)&hi0, *(uint32_t*)&hi1);
        uint2 LO = make_uint2(*(uint32_t*)&lo0, *(uint32_t*)&lo1);
        size_t hb = (size_t)(b * 16 + h) * 1024 + l;
        if (sec == 0) {
            __nv_bfloat16* o = q3 + hb * 192 + d;
            *(uint2*)(o) = HI; *(uint2*)(o + 64) = HI; *(uint2*)(o + 128) = LO;
        } else if (sec == 1) {
            __nv_bfloat16* o = k3 + hb * 192 + d;
            *(uint2*)(o) = HI; *(uint2*)(o + 64) = LO; *(uint2*)(o + 128) = HI;
        } else {
            *(uint2*)(vh + hb * 64 + d) = HI;
        }
    }
}

// ---------------------------------------------------------------------------
// 5) mma.sync bf16 GEMM: C[M,N] = A3[M,K3] . W3[N,K3]^T
//    128x128 tile, BK=64, 8 warps (2x4), warp 64x32, 3-stage cp.async
//    MODE 0: fp32 out (+res). MODE 1: swiglu(gate)*acc -> bf16 triple out3
// ---------------------------------------------------------------------------
#define ASTRIDE   144                     // 64 bf16 = 128B + 16 pad
#define TILEB     (128 * ASTRIDE)         // 18432
#define GEMM_SMEM (3 * 2 * TILEB)         // 110592

template<int MODE>
__global__ __launch_bounds__(256, 2) void k_gemm_mma(
        const __nv_bfloat16* __restrict__ A,
        const __nv_bfloat16* __restrict__ Bw,
        const float* __restrict__ res,      // residual (MODE0) or gate (MODE1)
        float* __restrict__ C,              // MODE0 out
        __nv_bfloat16* __restrict__ out3,   // MODE1 out (triple)
        int N, int K3) {
    extern __shared__ char smem[];
    uint32_t sb = smem_u32(smem);
    int tid = threadIdx.x, lane = tid & 31, wid = tid >> 5;
    int wm = wid >> 2, wn = wid & 3;
    int bm = blockIdx.y * 128, bn = blockIdx.x * 128;

    int crow = tid >> 1;
    int chalf = tid & 1;
    const __nv_bfloat16* gA = A  + (size_t)(bm + crow) * K3 + chalf * 32;
    const __nv_bfloat16* gB = Bw + (size_t)(bn + crow) * K3 + chalf * 32;
    uint32_t sOff = crow * ASTRIDE + chalf * 64;

    uint32_t aOff = (uint32_t)((lane & 15) * ASTRIDE + (lane >> 4) * 16);
    uint32_t bOff = (uint32_t)(((lane & 7) + ((lane >> 4) & 1) * 8) * ASTRIDE
                               + ((lane >> 3) & 1) * 16);

    float acc[4][4][4] = {};
    int niter = K3 >> 6;

    #pragma unroll
    for (int p = 0; p < 2; p++) {
        uint32_t as = sb + p * 2 * TILEB + sOff;
        const __nv_bfloat16* ag = gA + p * 64;
        const __nv_bfloat16* bg = gB + p * 64;
        #pragma unroll
        for (int i = 0; i < 4; i++) {
            cp16(as + i * 16,         ag + i * 8);
            cp16(as + TILEB + i * 16, bg + i * 8);
        }
        cp_commit();
    }

    for (int it = 0; it < niter; it++) {
        cp_wait1();
        __syncthreads();
        int nx = it + 2;
        if (nx < niter) {
            uint32_t as = sb + (nx % 3) * 2 * TILEB + sOff;
            const __nv_bfloat16* ag = gA + nx * 64;
            const __nv_bfloat16* bg = gB + nx * 64;
            #pragma unroll
            for (int i = 0; i < 4; i++) {
                cp16(as + i * 16,         ag + i * 8);
                cp16(as + TILEB + i * 16, bg + i * 8);
            }
        }
        cp_commit();

        uint32_t Ab = sb + (it % 3) * 2 * TILEB;
        uint32_t Bb = Ab + TILEB;
        #pragma unroll
        for (int ks = 0; ks < 4; ks++) {
            uint32_t a[4][4];
            #pragma unroll
            for (int am = 0; am < 4; am++)
                ldsm4(a[am], Ab + (wm * 64 + am * 16) * ASTRIDE + ks * 32 + aOff);
            uint32_t b[2][4];
            #pragma unroll
            for (int bg2 = 0; bg2 < 2; bg2++)
                ldsm4(b[bg2], Bb + (wn * 32 + bg2 * 16) * ASTRIDE + ks * 32 + bOff);
            #pragma unroll
            for (int am = 0; am < 4; am++)
                #pragma unroll
                for (int bnn = 0; bnn < 4; bnn++)
                    mma16816(acc[am][bnn], a[am],
                             b[bnn >> 1][(bnn & 1) * 2], b[bnn >> 1][(bnn & 1) * 2 + 1]);
        }
    }

    int g = lane >> 2;
    int mbase = bm + wm * 64;
    int nbase = bn + wn * 32 + (lane & 3) * 2;
    #pragma unroll
    for (int am = 0; am < 4; am++) {
        #pragma unroll
        for (int bnn = 0; bnn < 4; bnn++) {
            int row0 = mbase + am * 16 + g;
            int col  = nbase + bnn * 8;
            size_t o0 = (size_t)row0 * N + col;
            size_t o1 = (size_t)(row0 + 8) * N + col;
            float2 v0 = {acc[am][bnn][0], acc[am][bnn][1]};
            float2 v1 = {acc[am][bnn][2], acc[am][bnn][3]};
            if (MODE == 0) {
                if (res) {
                    float2 r0 = *(const float2*)(res + o0);
                    float2 r1 = *(const float2*)(res + o1);
                    v0.x += r0.x; v0.y += r0.y;
                    v1.x += r1.x; v1.y += r1.y;
                }
                *(float2*)(C + o0) = v0;
                *(float2*)(C + o1) = v1;
            } else {
                float2 g0 = *(const float2*)(res + o0);
                float2 g1 = *(const float2*)(res + o1);
                float a0 = g0.x / (1.f + __expf(-g0.x)) * v0.x;
                float a1 = g0.y / (1.f + __expf(-g0.y)) * v0.y;
                float a2 = g1.x / (1.f + __expf(-g1.x)) * v1.x;
                float a3 = g1.y / (1.f + __expf(-g1.y)) * v1.y;
                __nv_bfloat16 h0, l0, h1, l1, h2, l2, h3, l3;
                split2(a0, h0, l0); split2(a1, h1, l1);
                split2(a2, h2, l2); split2(a3, h3, l3);
                __nv_bfloat162 hp0 = {h0, h1}, lp0 = {l0, l1};
                __nv_bfloat162 hp1 = {h2, h3}, lp1 = {l2, l3};
                __nv_bfloat16* op0 = out3 + (size_t)row0 * 3 * N + col;
                __nv_bfloat16* op1 = out3 + (size_t)(row0 + 8) * 3 * N + col;
                *(uint32_t*)(op0)         = *(uint32_t*)&hp0;
                *(uint32_t*)(op0 + N)     = *(uint32_t*)&hp0;
                *(uint32_t*)(op0 + 2 * N) = *(uint32_t*)&lp0;
                *(uint32_t*)(op1)         = *(uint32_t*)&hp1;
                *(uint32_t*)(op1 + N)     = *(uint32_t*)&hp1;
                *(uint32_t*)(op1 + 2 * N) = *(uint32_t*)&lp1;
            }
        }
    }
}

// ---------------------------------------------------------------------------
// 6) fused flash attention (tensor core), writes d_ao3 (hi|hi|lo) directly
//    grid (qt=16, bh=128), 128 threads (4 warps, 16 q-rows each)
// ---------------------------------------------------------------------------
#define QSTR 400                          // 192 bf16 = 384B + 16
#define VSTR 144
#define FL_QOFF 0
#define FL_KOFF 25600
#define FL_VOFF 76800
#define FLASH_SMEM 95232

__global__ __launch_bounds__(128) void k_flash(
        const __nv_bfloat16* __restrict__ q3h, const __nv_bfloat16* __restrict__ k3h,
        const __nv_bfloat16* __restrict__ vhh, __nv_bfloat16* __restrict__ ao3) {
    extern __shared__ char smem[];
    uint32_t sb = smem_u32(smem);
    int tid = threadIdx.x, lane = tid & 31, w = tid >> 5;
    int qt = blockIdx.x, bh = blockIdx.y;
    int b = bh >> 4, h = bh & 15;
    const __nv_bfloat16* qg = q3h + (size_t)bh * L_ * 192 + (size_t)(qt * 64) * 192;
    const __nv_bfloat16* kg = k3h + (size_t)bh * L_ * 192;
    const __nv_bfloat16* vg = vhh + (size_t)bh * L_ * 64;

    int lrow2 = tid >> 1;
    int lhalf = tid & 1;

    // Q load (group 0)
    {
        uint32_t qs = sb + FL_QOFF + lrow2 * QSTR + lhalf * 192;
        const char* src = (const char*)(qg + (size_t)lrow2 * 192) + lhalf * 192;
        #pragma unroll
        for (int i = 0; i < 12; i++) cp16(qs + i * 16, src + i * 16);
    }
    auto loadKV = [&](int t, int buf) {
        uint32_t ks = sb + FL_KOFF + buf * 25600 + lrow2 * QSTR + lhalf * 192;
        const char* ksrc = (const char*)(kg + (size_t)(t * 64 + lrow2) * 192) + lhalf * 192;
        #pragma unroll
        for (int i = 0; i < 12; i++) cp16(ks + i * 16, ksrc + i * 16);
        uint32_t vs = sb + FL_VOFF + buf * 9216 + lrow2 * VSTR + lhalf * 64;
        const char* vsrc = (const char*)(vg + (size_t)(t * 64 + lrow2) * 64) + lhalf * 64;
        #pragma unroll
        for (int i = 0; i < 4; i++) cp16(vs + i * 16, vsrc + i * 16);
    };
    loadKV(0, 0); cp_commit();
    loadKV(1, 1); cp_commit();

    float qm[2] = {-1e30f, -1e30f};
    float ll[2] = {0.f, 0.f};
    float o[8][4] = {};
    uint32_t qf[12][4];
    uint32_t aAddrQ = sb + FL_QOFF + (w * 16 + (lane & 15)) * QSTR + (lane >> 4) * 16;
    uint32_t bOffK = ((lane & 7) + ((lane >> 4) & 1) * 8) * QSTR + ((lane >> 3) & 1) * 16;
    uint32_t vOffT = (lane & 15) * VSTR + (lane >> 4) * 16;

    for (int t = 0; t < 16; t++) {
        if (t < 15) cp_wait1(); else cp_wait0();
        __syncthreads();
        if (t == 0) {
            #pragma unroll
            for (int ks = 0; ks < 12; ks++) ldsm4(qf[ks], aAddrQ + ks * 32);
        }
        uint32_t Kb = sb + FL_KOFF + (t & 1) * 25600;
        uint32_t Vb = sb + FL_VOFF + (t & 1) * 9216;

        float s[8][4] = {};
        #pragma unroll
        for (int ks = 0; ks < 12; ks++) {
            #pragma unroll
            for (int nb2 = 0; nb2 < 4; nb2++) {
                uint32_t bf[4];
                ldsm4(bf, Kb + bOffK + nb2 * 16 * QSTR + ks * 32);
                mma16816(s[nb2 * 2],     qf[ks], bf[0], bf[1]);
                mma16816(s[nb2 * 2 + 1], qf[ks], bf[2], bf[3]);
            }
        }
        // online softmax
        float mx0 = -1e30f, mx1 = -1e30f;
        #pragma unroll
        for (int nb = 0; nb < 8; nb++) {
            #pragma unroll
            for (int e = 0; e < 4; e++) s[nb][e] *= 0.125f;
            mx0 = fmaxf(mx0, fmaxf(s[nb][0], s[nb][1]));
            mx1 = fmaxf(mx1, fmaxf(s[nb][2], s[nb][3]));
        }
        mx0 = fmaxf(mx0, __shfl_xor_sync(0xffffffffu, mx0, 1));
        mx0 = fmaxf(mx0, __shfl_xor_sync(0xffffffffu, mx0, 2));
        mx1 = fmaxf(mx1, __shfl_xor_sync(0xffffffffu, mx1, 1));
        mx1 = fmaxf(mx1, __shfl_xor_sync(0xffffffffu, mx1, 2));
        float mn0 = fmaxf(qm[0], mx0), mn1 = fmaxf(qm[1], mx1);
        float cf0 = __expf(qm[0] - mn0), cf1 = __expf(qm[1] - mn1);
        qm[0] = mn0; qm[1] = mn1;
        float sum0 = 0.f, sum1 = 0.f;
        #pragma unroll
        for (int nb = 0; nb < 8; nb++) {
            s[nb][0] = __expf(s[nb][0] - mn0);
            s[nb][1] = __expf(s[nb][1] - mn0);
            s[nb][2] = __expf(s[nb][2] - mn1);
            s[nb][3] = __expf(s[nb][3] - mn1);
            sum0 += s[nb][0] + s[nb][1];
            sum1 += s[nb][2] + s[nb][3];
        }
        sum0 += __shfl_xor_sync(0xffffffffu, sum0, 1);
        sum0 += __shfl_xor_sync(0xffffffffu, sum0, 2);
        sum1 += __shfl_xor_sync(0xffffffffu, sum1, 1);
        sum1 += __shfl_xor_sync(0xffffffffu, sum1, 2);
        ll[0] = ll[0] * cf0 + sum0;
        ll[1] = ll[1] * cf1 + sum1;
        #pragma unroll
        for (int nb = 0; nb < 8; nb++) {
            o[nb][0] *= cf0; o[nb][1] *= cf0;
            o[nb][2] *= cf1; o[nb][3] *= cf1;
        }
        // P fragments (bf16)
        uint32_t pf[4][4];
        #pragma unroll
        for (int kb = 0; kb < 4; kb++) {
            pf[kb][0] = packbf(s[2 * kb][0],     s[2 * kb][1]);
            pf[kb][1] = packbf(s[2 * kb][2],     s[2 * kb][3]);
            pf[kb][2] = packbf(s[2 * kb + 1][0], s[2 * kb + 1][1]);
            pf[kb][3] = packbf(s[2 * kb + 1][2], s[2 * kb + 1][3]);
        }
        // O += P . V
        #pragma unroll
        for (int kb = 0; kb < 4; kb++) {
            #pragma unroll
            for (int nbp = 0; nbp < 4; nbp++) {
                uint32_t vf[4];
                ldsm4t(vf, Vb + vOffT + kb * 16 * VSTR + nbp * 32);
                mma16816(o[nbp * 2],     pf[kb], vf[0], vf[1]);
                mma16816(o[nbp * 2 + 1], pf[kb], vf[2], vf[3]);
            }
        }
        __syncthreads();
        if (t + 2 < 16) { loadKV(t + 2, t & 1); cp_commit(); }
    }

    // epilogue: O/l -> ao3 (hi|hi|lo)
    int g = lane >> 2;
    float inv0 = 1.f / ll[0], inv1 = 1.f / ll[1];
    int lr0 = qt * 64 + w * 16 + g;
    size_t base0 = ((size_t)(b * 1024 + lr0)) * K3D_ + h * 64;
    size_t base1 = ((size_t)(b * 1024 + lr0 + 8)) * K3D_ + h * 64;
    #pragma unroll
    for (int nb = 0; nb < 8; nb++) {
        int c = nb * 8 + (lane & 3) * 2;
        float v0 = o[nb][0] * inv0, v1 = o[nb][1] * inv0;
        float v2 = o[nb][2] * inv1, v3 = o[nb][3] * inv1;
        __nv_bfloat16 h0, l0x, h1, l1x, h2, l2x, h3, l3x;
        split2(v0, h0, l0x); split2(v1, h1, l1x);
        split2(v2, h2, l2x); split2(v3, h3, l3x);
        __nv_bfloat162 hp0 = {h0, h1}, lp0 = {l0x, l1x};
        __nv_bfloat162 hp1 = {h2, h3}, lp1 = {l2x, l3x};
        *(uint32_t*)(ao3 + base0 + c)        = *(uint32_t*)&hp0;
        *(uint32_t*)(ao3 + base0 + 1024 + c) = *(uint32_t*)&hp0;
        *(uint32_t*)(ao3 + base0 + 2048 + c) = *(uint32_t*)&lp0;
        *(uint32_t*)(ao3 + base1 + c)        = *(uint32_t*)&hp1;
        *(uint32_t*)(ao3 + base1 + 1024 + c) = *(uint32_t*)&hp1;
        *(uint32_t*)(ao3 + base1 + 2048 + c) = *(uint32_t*)&lp1;
    }
}

// ---------------------------------------------------------------------------
// Host launcher
// ---------------------------------------------------------------------------
extern "C" void kernel_launch(void* const* d_in, const int* in_sizes, int n_in,
                              void* d_out, int out_size) {
    const float* x     = (const float*)d_in[0];
    const float* t     = (const float*)d_in[1];
    const float* Wq    = (const float*)d_in[2];
    const float* Wk    = (const float*)d_in[3];
    const float* Wv    = (const float*)d_in[4];
    const float* Wo    = (const float*)d_in[5];
    const float* g1w   = (const float*)d_in[6];
    const float* g1b   = (const float*)d_in[7];
    const float* b1w   = (const float*)d_in[8];
    const float* b1b   = (const float*)d_in[9];
    const float* g2w   = (const float*)d_in[10];
    const float* g2b   = (const float*)d_in[11];
    const float* b2w   = (const float*)d_in[12];
    const float* b2b   = (const float*)d_in[13];
    const float* gatew = (const float*)d_in[14];
    const float* hidw  = (const float*)d_in[15];
    const float* outw  = (const float*)d_in[16];
    float* out = (float*)d_out;

    float *qkv, *x1, *gate;
    __nv_bfloat16 *xn3, *ao3, *ga3, *q3, *k3, *vh, *wqkv3, *wo3, *wg3, *wh3, *wu3;
    cudaGetSymbolAddress((void**)&qkv,   d_qkv);
    cudaGetSymbolAddress((void**)&x1,    d_x1);
    cudaGetSymbolAddress((void**)&gate,  d_gate);
    cudaGetSymbolAddress((void**)&xn3,   d_xn3);
    cudaGetSymbolAddress((void**)&ao3,   d_ao3);
    cudaGetSymbolAddress((void**)&ga3,   d_ga3);
    cudaGetSymbolAddress((void**)&q3,    d_q3);
    cudaGetSymbolAddress((void**)&k3,    d_k3);
    cudaGetSymbolAddress((void**)&vh,    d_vh);
    cudaGetSymbolAddress((void**)&wqkv3, d_wqkv3);
    cudaGetSymbolAddress((void**)&wo3,   d_wo3);
    cudaGetSymbolAddress((void**)&wg3,   d_wg3);
    cudaGetSymbolAddress((void**)&wh3,   d_wh3);
    cudaGetSymbolAddress((void**)&wu3,   d_wu3);

    cudaFuncSetAttribute(k_gemm_mma<0>, cudaFuncAttributeMaxDynamicSharedMemorySize, GEMM_SMEM);
    cudaFuncSetAttribute(k_gemm_mma<1>, cudaFuncAttributeMaxDynamicSharedMemorySize, GEMM_SMEM);
    cudaFuncSetAttribute(k_flash, cudaFuncAttributeMaxDynamicSharedMemorySize, FLASH_SMEM);

    // weight conversions (hi|lo|hi)
    k_cvt3<<<(D_ * D_ / 4) / 256, 256>>>(Wq, wqkv3, D_);
    k_cvt3<<<(D_ * D_ / 4) / 256, 256>>>(Wk, wqkv3 + (size_t)D_ * K3D_, D_);
    k_cvt3<<<(D_ * D_ / 4) / 256, 256>>>(Wv, wqkv3 + (size_t)2 * D_ * K3D_, D_);
    k_cvt3<<<(D_ * D_ / 4) / 256, 256>>>(Wo, wo3, D_);
    k_cvt3<<<(HID_ * D_ / 4) / 256, 256>>>(gatew, wg3, D_);
    k_cvt3<<<(HID_ * D_ / 4) / 256, 256>>>(hidw,  wh3, D_);
    k_cvt3<<<(D_ * HID_ / 4) / 256, 256>>>(outw,  wu3, HID_);

    // gamma/beta + norm1 (fused convert)
    k_gamma_beta<<<128, 256>>>(t, g1w, g1b, b1w, b1b, g2w, g2b, b2w, b2b);
    k_rmsnorm_cvt<<<ROWS_, 256>>>(x, xn3, 0, 1);

    // fused QKV projection (one GEMM, N=3072)
    dim3 gqkv(3 * D_ / 128, ROWS_ / 128);   // (24, 64)
    dim3 gn1024(D_ / 128, ROWS_ / 128);     // (8, 64)
    dim3 gn4096(HID_ / 128, ROWS_ / 128);   // (32, 64)
    k_gemm_mma<0><<<gqkv, 256, GEMM_SMEM>>>(xn3, wqkv3, nullptr, qkv, nullptr, 3 * D_, K3D_);

    // per-head operand conversion + flash attention (writes ao3 directly)
    k_qkv3_cvt<<<ROWS_, 256>>>(qkv, q3, k3, vh);
    k_flash<<<dim3(L_ / 64, BH_), 128, FLASH_SMEM>>>(q3, k3, vh, ao3);

    // output projection + residual
    k_gemm_mma<0><<<gn1024, 256, GEMM_SMEM>>>(ao3, wo3, x, x1, nullptr, D_, K3D_);

    // norm2 + MLP (swiglu fused into hid GEMM epilogue)
    k_rmsnorm_cvt<<<ROWS_, 256>>>(x1, xn3, 2, 3);
    k_gemm_mma<0><<<gn4096, 256, GEMM_SMEM>>>(xn3, wg3, nullptr, gate, nullptr, HID_, K3D_);
    k_gemm_mma<1><<<gn4096, 256, GEMM_SMEM>>>(xn3, wh3, gate, nullptr, ga3, HID_, K3D_);
    k_gemm_mma<0><<<gn1024, 256, GEMM_SMEM>>>(ga3, wu3, x1, out, nullptr, D_, K3H_);
}